// round 9
// baseline (speedup 1.0000x reference)
#include <cuda_runtime.h>
#include <math.h>

#define SEQ 17520
#define NB 16
#define NCH 64
#define CHUNK 48
#define NCHK 365   // 365*48 = 17520 exactly

typedef unsigned long long u64;

// ---------------- device scratch (no allocation allowed) ----------------
__device__ float4 g_pre4[SEQ * NCH];            // [t_exec][chain] gate affines (i,f,o pre-halved)
__device__ float  g_hraw[SEQ * NCH];            // [t_exec][chain] raw hidden states
__device__ float  g_hT[SEQ * 32];               // encoder output, transposed [t][m]
__device__ float  g_bufA[13140 * 32];           // activations [n][32]
__device__ float  g_bufB[8760 * 32];
__device__ float  g_zi2[1752 * 32];
__device__ float  g_zc4[10 * 32];
__device__ float  g_part[5300000];              // split-K partials [split][tile][n(256)][m(32)]

// ---------------- helpers ----------------
__device__ __forceinline__ float tanhf_a(float x) {
    float y; asm("tanh.approx.f32 %0, %1;" : "=f"(y) : "f"(x)); return y;
}
__device__ __forceinline__ u64 ffma2(u64 a, u64 b, u64 c) {
    u64 d; asm("fma.rn.f32x2 %0, %1, %2, %3;" : "=l"(d) : "l"(a), "l"(b), "l"(c)); return d;
}
__device__ __forceinline__ u64 dup2(float x) {
    u64 d; unsigned ux = __float_as_uint(x);
    asm("mov.b64 %0, {%1, %1};" : "=l"(d) : "r"(ux)); return d;
}

// ---------------- 1. gate-affine precompute (i,f,o halved for tanh-sigmoid) ----------------
__global__ void pre_kernel(const float* __restrict__ x_t, const float* __restrict__ x_aug,
                           const float* __restrict__ Wih_f, const float* __restrict__ b_f,
                           const float* __restrict__ Wih_b, const float* __restrict__ b_b) {
    int idx = blockIdx.x * 256 + threadIdx.x;   // exactly SEQ*64 threads
    int c = idx & 63, t = idx >> 6;
    int in = c >> 5, dir = (c >> 4) & 1, b = c & 15;
    const float* x   = in  ? x_aug : x_t;
    const float* Wih = dir ? Wih_b : Wih_f;
    const float* bb  = dir ? b_b   : b_f;
    float xv = x[b * SEQ + (dir ? (SEQ - 1 - t) : t)];
    float4 o;
    o.x = 0.5f * fmaf(xv, Wih[0], bb[0]);   // i
    o.y = 0.5f * fmaf(xv, Wih[1], bb[1]);   // f
    o.z =        fmaf(xv, Wih[2], bb[2]);   // g (full scale, genuine tanh)
    o.w = 0.5f * fmaf(xv, Wih[3], bb[3]);   // o
    g_pre4[t * NCH + c] = o;
}

// ---------------- 2. LSTM recurrence: warp-specialized, smem-staged (R5 exact) ----------------
extern __shared__ char dynsmem[];

__device__ __forceinline__ void lstm_step(float4 p, float& h, float& C,
                                          float wi2, float wf2, float wg, float wo2) {
    float ti = tanhf_a(fmaf(h, wi2, p.x));
    float tf = tanhf_a(fmaf(h, wf2, p.y));
    float tg = tanhf_a(fmaf(h, wg,  p.z));
    float to = tanhf_a(fmaf(h, wo2, p.w));
    float i = fmaf(ti, 0.5f, 0.5f);         // sigmoid via tanh(x/2)
    float f = fmaf(tf, 0.5f, 0.5f);
    float o = fmaf(to, 0.5f, 0.5f);
    C = fmaf(f, C, i * tg);
    h = o * tanhf_a(C);
}

__global__ void __launch_bounds__(256, 1)
lstm_kernel(const float* __restrict__ Whh_f, const float* __restrict__ Whh_b) {
    float4* sbuf = (float4*)dynsmem;                               // [2][CHUNK*64]
    float*  sh   = (float*)(dynsmem + 2 * CHUNK * 64 * 16);        // [2][CHUNK*64]
    int tid = threadIdx.x;

    if (tid >= 64) {                       // producers: prologue fill of chunk 0
        int pt = tid - 64;
        const float4* src = (const float4*)g_pre4;
        for (int i = pt; i < CHUNK * 64; i += 192) sbuf[i] = src[i];
    }
    __syncthreads();

    if (tid < 64) {
        // ---- consumer: one chain per thread ----
        int c = tid;
        int dir = (c >> 4) & 1;
        const float* Whh = dir ? Whh_b : Whh_f;
        float wi2 = 0.5f * Whh[0], wf2 = 0.5f * Whh[1];
        float wg  =        Whh[2], wo2 = 0.5f * Whh[3];
        float h = 0.0f, C = 0.0f;
        for (int ch = 0; ch < NCHK; ++ch) {
            int cur = ch & 1;
            const float4* buf = sbuf + cur * CHUNK * 64;
            float* hdst = sh + cur * CHUNK * 64;
            float4 p = buf[c];
#pragma unroll 4
            for (int s = 0; s < CHUNK; ++s) {
                float4 pn = buf[(s + 1) * 64 + c];   // s=CHUNK-1 reads harmless in-smem data
                lstm_step(p, h, C, wi2, wf2, wg, wo2);
                hdst[s * 64 + c] = h;
                p = pn;
            }
            __syncthreads();
        }
    } else {
        // ---- producer ----
        int pt = tid - 64;
        const float4* src = (const float4*)g_pre4;
        for (int ch = 0; ch < NCHK; ++ch) {
            int cur = ch & 1, nxt = cur ^ 1;
            if (ch + 1 < NCHK) {
                const float4* s4 = src + (size_t)(ch + 1) * CHUNK * 64;
                float4* d4 = sbuf + nxt * CHUNK * 64;
                for (int i = pt; i < CHUNK * 64; i += 192) d4[i] = s4[i];
            }
            if (ch >= 1) {
                const float* hs = sh + nxt * CHUNK * 64;       // chunk ch-1 parity
                float* gd = g_hraw + (size_t)(ch - 1) * CHUNK * 64;
                for (int i = pt; i < CHUNK * 64; i += 192) gd[i] = hs[i];
            }
            __syncthreads();
        }
        const float* hs = sh + ((NCHK - 1) & 1) * CHUNK * 64;
        float* gd = g_hraw + (size_t)(NCHK - 1) * CHUNK * 64;
        for (int i = pt; i < CHUNK * 64; i += 192) gd[i] = hs[i];
    }
}

// ---------------- 3. direction combine -> h_enc^T [t][m], m = in*16+b ----------------
__global__ void combine_kernel(const float* __restrict__ Wl, const float* __restrict__ bl) {
    int idx = blockIdx.x * 256 + threadIdx.x;   // exactly SEQ*32
    int t = idx >> 5, m = idx & 31;
    int in = m >> 4, b = m & 15;
    float hf = g_hraw[(size_t)t * 64 + in * 32 + b];
    float hb = g_hraw[(size_t)(SEQ - 1 - t) * 64 + in * 32 + 16 + b];
    g_hT[idx] = fmaf(Wl[0], hf, fmaf(Wl[1], hb, bl[0]));
}

// ---------------- 4. GEMM: balanced 8n x 8m register tile, split-K ----------------
// tile N=256, M=32, Kc=32. thread (ng = t>>2 in 0..31, mg = t&3):
//   outputs n = ng + 32*j (j<8), m = mg*8 .. mg*8+7 (4 m-paired u64 acc per j).
__global__ void __launch_bounds__(128, 3)
gemm_kernel(const float* __restrict__ A, const float* __restrict__ W, int N, int K) {
    __shared__ float sW[256][36];    // [n][k], 144B rows -> compute loads cover all banks
    __shared__ float sA[32][32];     // [k][m]
    int t = threadIdx.x;
    int bt = blockIdx.x, bs = blockIdx.y;
    int ntiles = gridDim.x, nsp = gridDim.y;
    int n0 = bt * 256;
    int k0 = (int)(((long long)K * bs) / nsp) & ~3;
    int k1 = (bs == nsp - 1) ? K : ((int)(((long long)K * (bs + 1)) / nsp) & ~3);
    int tw = t >> 3, fq = (t & 7) * 4;          // fill indices
    int ng = t >> 2, mg = t & 3, m0 = mg * 8;   // compute indices

    u64 acc[8][4];
#pragma unroll
    for (int j = 0; j < 8; ++j)
#pragma unroll
        for (int i = 0; i < 4; ++i) acc[j][i] = 0ULL;

    for (int kb = k0; kb < k1; kb += 32) {
#pragma unroll
        for (int r = 0; r < 16; ++r) {          // W tile [256][32]
            int row = tw + 16 * r;
            int n = n0 + row;
            int kq = kb + fq;
            float4 v = make_float4(0.f, 0.f, 0.f, 0.f);
            if (n < N && kq < k1) v = *(const float4*)(W + (size_t)n * K + kq);
            *(float4*)&sW[row][fq] = v;
        }
#pragma unroll
        for (int r = 0; r < 2; ++r) {           // A tile [32][32]
            int sk = tw + 16 * r;
            int k = kb + sk;
            float4 v = make_float4(0.f, 0.f, 0.f, 0.f);
            if (k < k1) v = *(const float4*)(A + (size_t)k * 32 + fq);
            *(float4*)&sA[sk][fq] = v;
        }
        __syncthreads();
#pragma unroll
        for (int k4 = 0; k4 < 8; ++k4) {
            float4 a[4][2];                      // 4 k rows x 8 m (as 2 float4 = 4 u64)
#pragma unroll
            for (int kk = 0; kk < 4; ++kk) {
                a[kk][0] = *(const float4*)&sA[4 * k4 + kk][m0];
                a[kk][1] = *(const float4*)&sA[4 * k4 + kk][m0 + 4];
            }
#pragma unroll
            for (int j = 0; j < 8; ++j) {
                float4 w = *(const float4*)&sW[ng + 32 * j][4 * k4];
                u64 w0 = dup2(w.x), w1 = dup2(w.y), w2 = dup2(w.z), w3 = dup2(w.w);
                const u64* a0 = (const u64*)&a[0][0];
                const u64* a1 = (const u64*)&a[1][0];
                const u64* a2 = (const u64*)&a[2][0];
                const u64* a3 = (const u64*)&a[3][0];
#pragma unroll
                for (int i = 0; i < 4; ++i) {
                    acc[j][i] = ffma2(w0, a0[i], acc[j][i]);
                    acc[j][i] = ffma2(w1, a1[i], acc[j][i]);
                    acc[j][i] = ffma2(w2, a2[i], acc[j][i]);
                    acc[j][i] = ffma2(w3, a3[i], acc[j][i]);
                }
            }
        }
        __syncthreads();
    }
    // part layout: [split][tile][n(256)][m(32)]
    size_t base = (size_t)(bs * ntiles + bt) * 8192;
#pragma unroll
    for (int j = 0; j < 8; ++j) {
        size_t idx = base + (size_t)(ng + 32 * j) * 32 + m0;
#pragma unroll
        for (int i = 0; i < 4; ++i)
            *(u64*)&g_part[idx + 2 * i] = acc[j][i];
    }
}

// ---------------- 5. split-K reduce + bias -> out [n][32] (float4) ----------------
__global__ void reduce_kernel(const float* __restrict__ bias, float* __restrict__ out,
                              int N, int ntiles, int nsplit) {
    int q = blockIdx.x * 256 + threadIdx.x;     // one float4 per thread
    if (q >= N * 8) return;
    int n = q >> 3, m4 = (q & 7) * 4;
    int bt = n >> 8, nl = n & 255;
    float b = bias[n];
    float4 s = make_float4(b, b, b, b);
    for (int sp = 0; sp < nsplit; ++sp) {
        const float4 v = *(const float4*)&g_part[((size_t)(sp * ntiles + bt) * 256 + nl) * 32 + m4];
        s.x += v.x; s.y += v.y; s.z += v.z; s.w += v.w;
    }
    *(float4*)&out[(size_t)n * 32 + m4] = s;
}

// ---------------- 6. tiny final cluster GEMM (10 x 4380) ----------------
__global__ void cluster4_kernel(const float* __restrict__ W, const float* __restrict__ bias) {
    __shared__ float red[8][32];
    int n = blockIdx.x, t = threadIdx.x;
    int m = t & 31, seg = t >> 5;
    float s = 0.0f;
    for (int k = seg; k < 4380; k += 8)
        s += g_bufA[k * 32 + m] * W[n * 4380 + k];
    red[seg][m] = s;
    __syncthreads();
    if (seg == 0) {
        float tot = bias[n];
#pragma unroll
        for (int j = 0; j < 8; ++j) tot += red[j][m];
        g_zc4[n * 32 + m] = tot;
    }
}

// ---------------- 7. instance-head L2 normalize -> d_out ----------------
__global__ void norm_kernel(float* __restrict__ out) {
    __shared__ float red[256];
    int m = blockIdx.x;                         // 0..31
    float ss = 0.0f;
    for (int f = threadIdx.x; f < 1752; f += 256) {
        float v = g_zi2[f * 32 + m]; ss += v * v;
    }
    red[threadIdx.x] = ss; __syncthreads();
    for (int s = 128; s > 0; s >>= 1) {
        if (threadIdx.x < s) red[threadIdx.x] += red[threadIdx.x + s];
        __syncthreads();
    }
    float inv = 1.0f / fmaxf(sqrtf(red[0]), 1e-12f);
    int in = m >> 4, b = m & 15;
    float* dst = out + in * (16 * 1752) + b * 1752;
    for (int f = threadIdx.x; f < 1752; f += 256)
        dst[f] = g_zi2[f * 32 + m] * inv;
}

// ---------------- 8. cluster-head softmax -> d_out ----------------
__global__ void softmax_kernel(float* __restrict__ out) {
    int m = threadIdx.x;                        // 32 threads
    float v[10]; float mx = -1e30f;
#pragma unroll
    for (int c = 0; c < 10; ++c) { v[c] = g_zc4[c * 32 + m]; mx = fmaxf(mx, v[c]); }
    float sum = 0.0f;
#pragma unroll
    for (int c = 0; c < 10; ++c) { v[c] = __expf(v[c] - mx); sum += v[c]; }
    float inv = 1.0f / sum;
    int in = m >> 4, b = m & 15;
    float* dst = out + 2 * 16 * 1752 + in * 160 + b * 10;
#pragma unroll
    for (int c = 0; c < 10; ++c) dst[c] = v[c] * inv;
}

// ---------------- launch ----------------
extern "C" void kernel_launch(void* const* d_in, const int* in_sizes, int n_in,
                              void* d_out, int out_size) {
    const float* x_t   = (const float*)d_in[0];
    const float* x_aug = (const float*)d_in[1];
    const float* Wih_f = (const float*)d_in[2];
    const float* Whh_f = (const float*)d_in[3];
    const float* b_f   = (const float*)d_in[4];
    const float* Wih_b = (const float*)d_in[5];
    const float* Whh_b = (const float*)d_in[6];
    const float* b_b   = (const float*)d_in[7];
    const float* Wl    = (const float*)d_in[8];
    const float* bl    = (const float*)d_in[9];
    const float* Wi1   = (const float*)d_in[10];
    const float* bi1   = (const float*)d_in[11];
    const float* Wi2   = (const float*)d_in[12];
    const float* bi2   = (const float*)d_in[13];
    const float* Wc1   = (const float*)d_in[14];
    const float* bc1   = (const float*)d_in[15];
    const float* Wc2   = (const float*)d_in[16];
    const float* bc2   = (const float*)d_in[17];
    const float* Wc3   = (const float*)d_in[18];
    const float* bc3   = (const float*)d_in[19];
    const float* Wc4   = (const float*)d_in[20];
    const float* bc4   = (const float*)d_in[21];
    float* out = (float*)d_out;

    float* hT   = nullptr; cudaGetSymbolAddress((void**)&hT,   g_hT);
    float* bufA = nullptr; cudaGetSymbolAddress((void**)&bufA, g_bufA);
    float* bufB = nullptr; cudaGetSymbolAddress((void**)&bufB, g_bufB);
    float* zi2  = nullptr; cudaGetSymbolAddress((void**)&zi2,  g_zi2);

    static bool attr_done = false;
    if (!attr_done) {
        cudaFuncSetAttribute(lstm_kernel, cudaFuncAttributeMaxDynamicSharedMemorySize, 122880);
        attr_done = true;
    }

    // encoder
    pre_kernel<<<(SEQ * NCH) / 256, 256>>>(x_t, x_aug, Wih_f, b_f, Wih_b, b_b);
    lstm_kernel<<<1, 256, 122880>>>(Whh_f, Whh_b);
    combine_kernel<<<(SEQ * 32) / 256, 256>>>(Wl, bl);

    // instance head: 17520 -> 8760 -> 1752
    gemm_kernel<<<dim3(35, 17), 128>>>(hT, Wi1, 8760, 17520);
    reduce_kernel<<<(8760 * 8 + 255) / 256, 256>>>(bi1, bufB, 8760, 35, 17);
    gemm_kernel<<<dim3(7, 48), 128>>>(bufB, Wi2, 1752, 8760);
    reduce_kernel<<<(1752 * 8 + 255) / 256, 256>>>(bi2, zi2, 1752, 7, 48);

    // cluster head: 17520 -> 13140 -> 8760 -> 4380 -> 10
    gemm_kernel<<<dim3(52, 12), 128>>>(hT, Wc1, 13140, 17520);
    reduce_kernel<<<(13140 * 8 + 255) / 256, 256>>>(bc1, bufA, 13140, 52, 12);
    gemm_kernel<<<dim3(35, 17), 128>>>(bufA, Wc2, 8760, 13140);
    reduce_kernel<<<(8760 * 8 + 255) / 256, 256>>>(bc2, bufB, 8760, 35, 17);
    gemm_kernel<<<dim3(18, 33), 128>>>(bufB, Wc3, 4380, 8760);
    reduce_kernel<<<(4380 * 8 + 255) / 256, 256>>>(bc3, bufA, 4380, 18, 33);
    cluster4_kernel<<<10, 256>>>(Wc4, bc4);

    // epilogues
    norm_kernel<<<32, 256>>>(out);
    softmax_kernel<<<1, 32>>>(out);
}

// round 10
// speedup vs baseline: 1.1102x; 1.1102x over previous
#include <cuda_runtime.h>
#include <math.h>

#define SEQ 17520
#define NB 16
#define NCH 64
#define CHUNK 48
#define NCHK 365   // 365*48 = 17520 exactly

typedef unsigned long long u64;

// ---------------- device scratch (no allocation allowed) ----------------
__device__ float4 g_pre4[SEQ * NCH];            // [t_exec][chain] gate affines (i,f,o pre-halved)
__device__ float  g_hraw[SEQ * NCH];            // [t_exec][chain] raw hidden states
__device__ float  g_hT[SEQ * 32];               // encoder output, transposed [t][m]
__device__ float  g_bufA[13140 * 32];           // activations [n][32]
__device__ float  g_bufB[8760 * 32];
__device__ float  g_zi2[1752 * 32];
__device__ float  g_zc4[10 * 32];
__device__ float  g_part[2543616];              // split-K partials (max 621 tiles * 4096)

// ---------------- helpers ----------------
__device__ __forceinline__ float tanhf_a(float x) {
    float y; asm("tanh.approx.f32 %0, %1;" : "=f"(y) : "f"(x)); return y;
}
__device__ __forceinline__ u64 ffma2(u64 a, u64 b, u64 c) {
    u64 d; asm("fma.rn.f32x2 %0, %1, %2, %3;" : "=l"(d) : "l"(a), "l"(b), "l"(c)); return d;
}
__device__ __forceinline__ u64 pack2(float x, float y) {
    u64 d; unsigned ux = __float_as_uint(x), uy = __float_as_uint(y);
    asm("mov.b64 %0, {%1, %2};" : "=l"(d) : "r"(ux), "r"(uy)); return d;
}
__device__ __forceinline__ u64 dup2(float x) {
    u64 d; unsigned ux = __float_as_uint(x);
    asm("mov.b64 %0, {%1, %1};" : "=l"(d) : "r"(ux)); return d;
}
__device__ __forceinline__ void cp16(void* dst_smem, const void* src_gmem, bool ok) {
    unsigned dst = (unsigned)__cvta_generic_to_shared(dst_smem);
    int sz = ok ? 16 : 0;
    asm volatile("cp.async.cg.shared.global [%0], [%1], 16, %2;"
                 :: "r"(dst), "l"(src_gmem), "r"(sz));
}
__device__ __forceinline__ void cp_commit() {
    asm volatile("cp.async.commit_group;");
}

// ---------------- 1. gate-affine precompute (i,f,o halved for tanh-sigmoid) ----------------
__global__ void pre_kernel(const float* __restrict__ x_t, const float* __restrict__ x_aug,
                           const float* __restrict__ Wih_f, const float* __restrict__ b_f,
                           const float* __restrict__ Wih_b, const float* __restrict__ b_b) {
    int idx = blockIdx.x * 256 + threadIdx.x;   // exactly SEQ*64 threads
    int c = idx & 63, t = idx >> 6;
    int in = c >> 5, dir = (c >> 4) & 1, b = c & 15;
    const float* x   = in  ? x_aug : x_t;
    const float* Wih = dir ? Wih_b : Wih_f;
    const float* bb  = dir ? b_b   : b_f;
    float xv = x[b * SEQ + (dir ? (SEQ - 1 - t) : t)];
    float4 o;
    o.x = 0.5f * fmaf(xv, Wih[0], bb[0]);   // i
    o.y = 0.5f * fmaf(xv, Wih[1], bb[1]);   // f
    o.z =        fmaf(xv, Wih[2], bb[2]);   // g (full scale, genuine tanh)
    o.w = 0.5f * fmaf(xv, Wih[3], bb[3]);   // o
    g_pre4[t * NCH + c] = o;
}

// ---------------- 2. LSTM recurrence: warp-specialized, smem-staged (R5 exact) ----------------
extern __shared__ char dynsmem[];

__device__ __forceinline__ void lstm_step(float4 p, float& h, float& C,
                                          float wi2, float wf2, float wg, float wo2) {
    float ti = tanhf_a(fmaf(h, wi2, p.x));
    float tf = tanhf_a(fmaf(h, wf2, p.y));
    float tg = tanhf_a(fmaf(h, wg,  p.z));
    float to = tanhf_a(fmaf(h, wo2, p.w));
    float i = fmaf(ti, 0.5f, 0.5f);         // sigmoid via tanh(x/2)
    float f = fmaf(tf, 0.5f, 0.5f);
    float o = fmaf(to, 0.5f, 0.5f);
    C = fmaf(f, C, i * tg);
    h = o * tanhf_a(C);
}

__global__ void __launch_bounds__(256, 1)
lstm_kernel(const float* __restrict__ Whh_f, const float* __restrict__ Whh_b) {
    float4* sbuf = (float4*)dynsmem;                               // [2][CHUNK*64]
    float*  sh   = (float*)(dynsmem + 2 * CHUNK * 64 * 16);        // [2][CHUNK*64]
    int tid = threadIdx.x;

    if (tid >= 64) {                       // producers: prologue fill of chunk 0
        int pt = tid - 64;
        const float4* src = (const float4*)g_pre4;
        for (int i = pt; i < CHUNK * 64; i += 192) sbuf[i] = src[i];
    }
    __syncthreads();

    if (tid < 64) {
        // ---- consumer: one chain per thread ----
        int c = tid;
        int dir = (c >> 4) & 1;
        const float* Whh = dir ? Whh_b : Whh_f;
        float wi2 = 0.5f * Whh[0], wf2 = 0.5f * Whh[1];
        float wg  =        Whh[2], wo2 = 0.5f * Whh[3];
        float h = 0.0f, C = 0.0f;
        for (int ch = 0; ch < NCHK; ++ch) {
            int cur = ch & 1;
            const float4* buf = sbuf + cur * CHUNK * 64;
            float* hdst = sh + cur * CHUNK * 64;
            float4 p = buf[c];
#pragma unroll 4
            for (int s = 0; s < CHUNK; ++s) {
                float4 pn = buf[(s + 1) * 64 + c];   // s=CHUNK-1 reads harmless in-smem data
                lstm_step(p, h, C, wi2, wf2, wg, wo2);
                hdst[s * 64 + c] = h;
                p = pn;
            }
            __syncthreads();
        }
    } else {
        // ---- producer ----
        int pt = tid - 64;
        const float4* src = (const float4*)g_pre4;
        for (int ch = 0; ch < NCHK; ++ch) {
            int cur = ch & 1, nxt = cur ^ 1;
            if (ch + 1 < NCHK) {
                const float4* s4 = src + (size_t)(ch + 1) * CHUNK * 64;
                float4* d4 = sbuf + nxt * CHUNK * 64;
                for (int i = pt; i < CHUNK * 64; i += 192) d4[i] = s4[i];
            }
            if (ch >= 1) {
                const float* hs = sh + nxt * CHUNK * 64;       // chunk ch-1 parity
                float* gd = g_hraw + (size_t)(ch - 1) * CHUNK * 64;
                for (int i = pt; i < CHUNK * 64; i += 192) gd[i] = hs[i];
            }
            __syncthreads();
        }
        const float* hs = sh + ((NCHK - 1) & 1) * CHUNK * 64;
        float* gd = g_hraw + (size_t)(NCHK - 1) * CHUNK * 64;
        for (int i = pt; i < CHUNK * 64; i += 192) gd[i] = hs[i];
    }
}

// ---------------- 3. direction combine -> h_enc^T [t][m], m = in*16+b ----------------
__global__ void combine_kernel(const float* __restrict__ Wl, const float* __restrict__ bl) {
    int idx = blockIdx.x * 256 + threadIdx.x;   // exactly SEQ*32
    int t = idx >> 5, m = idx & 31;
    int in = m >> 4, b = m & 15;
    float hf = g_hraw[(size_t)t * 64 + in * 32 + b];
    float hb = g_hraw[(size_t)(SEQ - 1 - t) * 64 + in * 32 + 16 + b];
    g_hT[idx] = fmaf(Wl[0], hf, fmaf(Wl[1], hb, bl[0]));
}

// ---------------- 4. GEMM: cp.async 2-stage pipeline, R5 tile, split-K ----------------
// tile N=128, M=32, Kc=32. thread: 8 N rows (stride 16) x 4 M cols (2 f32x2 acc).
__global__ void __launch_bounds__(128)
gemm_kernel(const float* __restrict__ A, const float* __restrict__ W, int N, int K) {
    __shared__ float sW[2][128][36];     // 36KB (rows 144B = 16B-aligned)
    __shared__ float sA[2][32][32];      // 8KB
    int t = threadIdx.x;
    int bt = blockIdx.x, bs = blockIdx.y;
    int ntiles = gridDim.x, nsp = gridDim.y;
    int n0 = bt * 128;
    int k0 = (int)(((long long)K * bs) / nsp) & ~3;
    int k1 = (bs == nsp - 1) ? K : ((int)(((long long)K * (bs + 1)) / nsp) & ~3);
    int tg = t >> 3, m0 = (t & 7) * 4;
    int nt = (k1 - k0 + 31) / 32;

    u64 acc[8][2];
#pragma unroll
    for (int j = 0; j < 8; ++j) { acc[j][0] = 0ULL; acc[j][1] = 0ULL; }

    // stage issuer: async-copy one 32-k tile into buffer `b`
    auto issue = [&](int b, int kb) {
#pragma unroll
        for (int r = 0; r < 8; ++r) {
            int n = n0 + tg + 16 * r;
            int kq = kb + m0;
            bool ok = (n < N) && (kq < k1);
            const float* src = ok ? (W + (size_t)n * K + kq) : W;
            cp16(&sW[b][tg + 16 * r][m0], src, ok);
        }
#pragma unroll
        for (int r = 0; r < 2; ++r) {
            int k = kb + tg + 16 * r;
            bool ok = (k < k1);
            const float* src = ok ? (A + (size_t)k * 32 + m0) : A;
            cp16(&sA[b][tg + 16 * r][m0], src, ok);
        }
        cp_commit();
    };

    issue(0, k0);                         // prologue
    for (int it = 0; it < nt; ++it) {
        int buf = it & 1;
        if (it + 1 < nt) {
            issue(buf ^ 1, k0 + (it + 1) * 32);
            asm volatile("cp.async.wait_group 1;");
        } else {
            asm volatile("cp.async.wait_group 0;");
        }
        __syncthreads();
#pragma unroll
        for (int k4 = 0; k4 < 8; ++k4) {
            float4 a0 = *(const float4*)&sA[buf][4 * k4 + 0][m0];
            float4 a1 = *(const float4*)&sA[buf][4 * k4 + 1][m0];
            float4 a2 = *(const float4*)&sA[buf][4 * k4 + 2][m0];
            float4 a3 = *(const float4*)&sA[buf][4 * k4 + 3][m0];
            u64 a0l = pack2(a0.x, a0.y), a0h = pack2(a0.z, a0.w);
            u64 a1l = pack2(a1.x, a1.y), a1h = pack2(a1.z, a1.w);
            u64 a2l = pack2(a2.x, a2.y), a2h = pack2(a2.z, a2.w);
            u64 a3l = pack2(a3.x, a3.y), a3h = pack2(a3.z, a3.w);
#pragma unroll
            for (int j = 0; j < 8; ++j) {
                float4 w = *(const float4*)&sW[buf][tg + 16 * j][4 * k4];
                u64 wx = dup2(w.x), wy = dup2(w.y), wz = dup2(w.z), ww = dup2(w.w);
                acc[j][0] = ffma2(wx, a0l, acc[j][0]); acc[j][1] = ffma2(wx, a0h, acc[j][1]);
                acc[j][0] = ffma2(wy, a1l, acc[j][0]); acc[j][1] = ffma2(wy, a1h, acc[j][1]);
                acc[j][0] = ffma2(wz, a2l, acc[j][0]); acc[j][1] = ffma2(wz, a2h, acc[j][1]);
                acc[j][0] = ffma2(ww, a3l, acc[j][0]); acc[j][1] = ffma2(ww, a3h, acc[j][1]);
            }
        }
        __syncthreads();
    }
    size_t base = (size_t)(bs * ntiles + bt) * 4096;
#pragma unroll
    for (int j = 0; j < 8; ++j) {
        size_t idx = base + (size_t)(tg + 16 * j) * 32 + m0;
        *(u64*)&g_part[idx]     = acc[j][0];
        *(u64*)&g_part[idx + 2] = acc[j][1];
    }
}

// ---------------- 5. split-K reduce + bias -> out [n][32] (float4) ----------------
__global__ void reduce_kernel(const float* __restrict__ bias, float* __restrict__ out,
                              int N, int ntiles, int nsplit) {
    int q = blockIdx.x * 256 + threadIdx.x;     // one float4 per thread
    if (q >= N * 8) return;
    int n = q >> 3, m4 = (q & 7) * 4;
    int bt = n >> 7, nl = n & 127;
    float b = bias[n];
    float4 s = make_float4(b, b, b, b);
    for (int sp = 0; sp < nsplit; ++sp) {
        const float4 v = *(const float4*)&g_part[((size_t)(sp * ntiles + bt) * 128 + nl) * 32 + m4];
        s.x += v.x; s.y += v.y; s.z += v.z; s.w += v.w;
    }
    *(float4*)&out[(size_t)n * 32 + m4] = s;
}

// ---------------- 6. tiny final cluster GEMM (10 x 4380) ----------------
__global__ void cluster4_kernel(const float* __restrict__ W, const float* __restrict__ bias) {
    __shared__ float red[8][32];
    int n = blockIdx.x, t = threadIdx.x;
    int m = t & 31, seg = t >> 5;
    float s = 0.0f;
    for (int k = seg; k < 4380; k += 8)
        s += g_bufA[k * 32 + m] * W[n * 4380 + k];
    red[seg][m] = s;
    __syncthreads();
    if (seg == 0) {
        float tot = bias[n];
#pragma unroll
        for (int j = 0; j < 8; ++j) tot += red[j][m];
        g_zc4[n * 32 + m] = tot;
    }
}

// ---------------- 7. instance-head L2 normalize -> d_out ----------------
__global__ void norm_kernel(float* __restrict__ out) {
    __shared__ float red[256];
    int m = blockIdx.x;                         // 0..31
    float ss = 0.0f;
    for (int f = threadIdx.x; f < 1752; f += 256) {
        float v = g_zi2[f * 32 + m]; ss += v * v;
    }
    red[threadIdx.x] = ss; __syncthreads();
    for (int s = 128; s > 0; s >>= 1) {
        if (threadIdx.x < s) red[threadIdx.x] += red[threadIdx.x + s];
        __syncthreads();
    }
    float inv = 1.0f / fmaxf(sqrtf(red[0]), 1e-12f);
    int in = m >> 4, b = m & 15;
    float* dst = out + in * (16 * 1752) + b * 1752;
    for (int f = threadIdx.x; f < 1752; f += 256)
        dst[f] = g_zi2[f * 32 + m] * inv;
}

// ---------------- 8. cluster-head softmax -> d_out ----------------
__global__ void softmax_kernel(float* __restrict__ out) {
    int m = threadIdx.x;                        // 32 threads
    float v[10]; float mx = -1e30f;
#pragma unroll
    for (int c = 0; c < 10; ++c) { v[c] = g_zc4[c * 32 + m]; mx = fmaxf(mx, v[c]); }
    float sum = 0.0f;
#pragma unroll
    for (int c = 0; c < 10; ++c) { v[c] = __expf(v[c] - mx); sum += v[c]; }
    float inv = 1.0f / sum;
    int in = m >> 4, b = m & 15;
    float* dst = out + 2 * 16 * 1752 + in * 160 + b * 10;
#pragma unroll
    for (int c = 0; c < 10; ++c) dst[c] = v[c] * inv;
}

// ---------------- launch ----------------
extern "C" void kernel_launch(void* const* d_in, const int* in_sizes, int n_in,
                              void* d_out, int out_size) {
    const float* x_t   = (const float*)d_in[0];
    const float* x_aug = (const float*)d_in[1];
    const float* Wih_f = (const float*)d_in[2];
    const float* Whh_f = (const float*)d_in[3];
    const float* b_f   = (const float*)d_in[4];
    const float* Wih_b = (const float*)d_in[5];
    const float* Whh_b = (const float*)d_in[6];
    const float* b_b   = (const float*)d_in[7];
    const float* Wl    = (const float*)d_in[8];
    const float* bl    = (const float*)d_in[9];
    const float* Wi1   = (const float*)d_in[10];
    const float* bi1   = (const float*)d_in[11];
    const float* Wi2   = (const float*)d_in[12];
    const float* bi2   = (const float*)d_in[13];
    const float* Wc1   = (const float*)d_in[14];
    const float* bc1   = (const float*)d_in[15];
    const float* Wc2   = (const float*)d_in[16];
    const float* bc2   = (const float*)d_in[17];
    const float* Wc3   = (const float*)d_in[18];
    const float* bc3   = (const float*)d_in[19];
    const float* Wc4   = (const float*)d_in[20];
    const float* bc4   = (const float*)d_in[21];
    float* out = (float*)d_out;

    float* hT   = nullptr; cudaGetSymbolAddress((void**)&hT,   g_hT);
    float* bufA = nullptr; cudaGetSymbolAddress((void**)&bufA, g_bufA);
    float* bufB = nullptr; cudaGetSymbolAddress((void**)&bufB, g_bufB);
    float* zi2  = nullptr; cudaGetSymbolAddress((void**)&zi2,  g_zi2);

    static bool attr_done = false;
    if (!attr_done) {
        cudaFuncSetAttribute(lstm_kernel, cudaFuncAttributeMaxDynamicSharedMemorySize, 122880);
        attr_done = true;
    }

    // encoder
    pre_kernel<<<(SEQ * NCH) / 256, 256>>>(x_t, x_aug, Wih_f, b_f, Wih_b, b_b);
    lstm_kernel<<<1, 256, 122880>>>(Whh_f, Whh_b);
    combine_kernel<<<(SEQ * 32) / 256, 256>>>(Wl, bl);

    // instance head: 17520 -> 8760 -> 1752
    gemm_kernel<<<dim3(69, 9), 128>>>(hT, Wi1, 8760, 17520);
    reduce_kernel<<<(8760 * 8 + 255) / 256, 256>>>(bi1, bufB, 8760, 69, 9);
    gemm_kernel<<<dim3(14, 42), 128>>>(bufB, Wi2, 1752, 8760);
    reduce_kernel<<<(1752 * 8 + 255) / 256, 256>>>(bi2, zi2, 1752, 14, 42);

    // cluster head: 17520 -> 13140 -> 8760 -> 4380 -> 10
    gemm_kernel<<<dim3(103, 6), 128>>>(hT, Wc1, 13140, 17520);
    reduce_kernel<<<(13140 * 8 + 255) / 256, 256>>>(bc1, bufA, 13140, 103, 6);
    gemm_kernel<<<dim3(69, 9), 128>>>(bufA, Wc2, 8760, 13140);
    reduce_kernel<<<(8760 * 8 + 255) / 256, 256>>>(bc2, bufB, 8760, 69, 9);
    gemm_kernel<<<dim3(35, 17), 128>>>(bufB, Wc3, 4380, 8760);
    reduce_kernel<<<(4380 * 8 + 255) / 256, 256>>>(bc3, bufA, 4380, 35, 17);
    cluster4_kernel<<<10, 256>>>(Wc4, bc4);

    // epilogues
    norm_kernel<<<32, 256>>>(out);
    softmax_kernel<<<1, 32>>>(out);
}

// round 11
// speedup vs baseline: 1.1877x; 1.0698x over previous
#include <cuda_runtime.h>
#include <math.h>

#define SEQ 17520
#define NB 16
#define NCH 64
#define CHUNK 48
#define NCHK 365   // 365*48 = 17520 exactly

typedef unsigned long long u64;

// ---------------- device scratch (no allocation allowed) ----------------
__device__ float4 g_pre4[SEQ * NCH];            // [t_exec][chain] gate affines (i,f,o pre-halved)
__device__ float  g_hraw[SEQ * NCH];            // [t_exec][chain] raw hidden states
__device__ float  g_hT[SEQ * 32];               // encoder output, transposed [t][m]
__device__ float  g_bufA[13140 * 32];           // activations [n][32]
__device__ float  g_bufB[8760 * 32];
__device__ float  g_zi2[1752 * 32];
__device__ float  g_zc4[10 * 32];
__device__ float  g_part[3200000];              // split-K partials (max 759 tiles * 4096)

// ---------------- helpers ----------------
__device__ __forceinline__ float tanhf_a(float x) {
    float y; asm("tanh.approx.f32 %0, %1;" : "=f"(y) : "f"(x)); return y;
}
__device__ __forceinline__ u64 ffma2(u64 a, u64 b, u64 c) {
    u64 d; asm("fma.rn.f32x2 %0, %1, %2, %3;" : "=l"(d) : "l"(a), "l"(b), "l"(c)); return d;
}
__device__ __forceinline__ u64 pack2(float x, float y) {
    u64 d; unsigned ux = __float_as_uint(x), uy = __float_as_uint(y);
    asm("mov.b64 %0, {%1, %2};" : "=l"(d) : "r"(ux), "r"(uy)); return d;
}
__device__ __forceinline__ u64 dup2(float x) {
    u64 d; unsigned ux = __float_as_uint(x);
    asm("mov.b64 %0, {%1, %1};" : "=l"(d) : "r"(ux)); return d;
}
__device__ __forceinline__ void cp16(void* dst_smem, const void* src_gmem, bool ok) {
    unsigned dst = (unsigned)__cvta_generic_to_shared(dst_smem);
    int sz = ok ? 16 : 0;
    asm volatile("cp.async.cg.shared.global [%0], [%1], 16, %2;"
                 :: "r"(dst), "l"(src_gmem), "r"(sz));
}
__device__ __forceinline__ void cp_commit() {
    asm volatile("cp.async.commit_group;");
}

// ---------------- 1. gate-affine precompute (i,f,o halved for tanh-sigmoid) ----------------
__global__ void pre_kernel(const float* __restrict__ x_t, const float* __restrict__ x_aug,
                           const float* __restrict__ Wih_f, const float* __restrict__ b_f,
                           const float* __restrict__ Wih_b, const float* __restrict__ b_b) {
    int idx = blockIdx.x * 256 + threadIdx.x;   // exactly SEQ*64 threads
    int c = idx & 63, t = idx >> 6;
    int in = c >> 5, dir = (c >> 4) & 1, b = c & 15;
    const float* x   = in  ? x_aug : x_t;
    const float* Wih = dir ? Wih_b : Wih_f;
    const float* bb  = dir ? b_b   : b_f;
    float xv = x[b * SEQ + (dir ? (SEQ - 1 - t) : t)];
    float4 o;
    o.x = 0.5f * fmaf(xv, Wih[0], bb[0]);   // i
    o.y = 0.5f * fmaf(xv, Wih[1], bb[1]);   // f
    o.z =        fmaf(xv, Wih[2], bb[2]);   // g (full scale, genuine tanh)
    o.w = 0.5f * fmaf(xv, Wih[3], bb[3]);   // o
    g_pre4[t * NCH + c] = o;
}

// ---------------- 2. LSTM recurrence: warp-specialized, smem-staged (R5 exact) ----------------
extern __shared__ char dynsmem[];

__device__ __forceinline__ void lstm_step(float4 p, float& h, float& C,
                                          float wi2, float wf2, float wg, float wo2) {
    float ti = tanhf_a(fmaf(h, wi2, p.x));
    float tf = tanhf_a(fmaf(h, wf2, p.y));
    float tg = tanhf_a(fmaf(h, wg,  p.z));
    float to = tanhf_a(fmaf(h, wo2, p.w));
    float i = fmaf(ti, 0.5f, 0.5f);         // sigmoid via tanh(x/2)
    float f = fmaf(tf, 0.5f, 0.5f);
    float o = fmaf(to, 0.5f, 0.5f);
    C = fmaf(f, C, i * tg);
    h = o * tanhf_a(C);
}

__global__ void __launch_bounds__(256, 1)
lstm_kernel(const float* __restrict__ Whh_f, const float* __restrict__ Whh_b) {
    float4* sbuf = (float4*)dynsmem;                               // [2][CHUNK*64]
    float*  sh   = (float*)(dynsmem + 2 * CHUNK * 64 * 16);        // [2][CHUNK*64]
    int tid = threadIdx.x;

    if (tid >= 64) {                       // producers: prologue fill of chunk 0
        int pt = tid - 64;
        const float4* src = (const float4*)g_pre4;
        for (int i = pt; i < CHUNK * 64; i += 192) sbuf[i] = src[i];
    }
    __syncthreads();

    if (tid < 64) {
        // ---- consumer: one chain per thread ----
        int c = tid;
        int dir = (c >> 4) & 1;
        const float* Whh = dir ? Whh_b : Whh_f;
        float wi2 = 0.5f * Whh[0], wf2 = 0.5f * Whh[1];
        float wg  =        Whh[2], wo2 = 0.5f * Whh[3];
        float h = 0.0f, C = 0.0f;
        for (int ch = 0; ch < NCHK; ++ch) {
            int cur = ch & 1;
            const float4* buf = sbuf + cur * CHUNK * 64;
            float* hdst = sh + cur * CHUNK * 64;
            float4 p = buf[c];
#pragma unroll 4
            for (int s = 0; s < CHUNK; ++s) {
                float4 pn = buf[(s + 1) * 64 + c];   // s=CHUNK-1 reads harmless in-smem data
                lstm_step(p, h, C, wi2, wf2, wg, wo2);
                hdst[s * 64 + c] = h;
                p = pn;
            }
            __syncthreads();
        }
    } else {
        // ---- producer ----
        int pt = tid - 64;
        const float4* src = (const float4*)g_pre4;
        for (int ch = 0; ch < NCHK; ++ch) {
            int cur = ch & 1, nxt = cur ^ 1;
            if (ch + 1 < NCHK) {
                const float4* s4 = src + (size_t)(ch + 1) * CHUNK * 64;
                float4* d4 = sbuf + nxt * CHUNK * 64;
                for (int i = pt; i < CHUNK * 64; i += 192) d4[i] = s4[i];
            }
            if (ch >= 1) {
                const float* hs = sh + nxt * CHUNK * 64;       // chunk ch-1 parity
                float* gd = g_hraw + (size_t)(ch - 1) * CHUNK * 64;
                for (int i = pt; i < CHUNK * 64; i += 192) gd[i] = hs[i];
            }
            __syncthreads();
        }
        const float* hs = sh + ((NCHK - 1) & 1) * CHUNK * 64;
        float* gd = g_hraw + (size_t)(NCHK - 1) * CHUNK * 64;
        for (int i = pt; i < CHUNK * 64; i += 192) gd[i] = hs[i];
    }
}

// ---------------- 3. direction combine -> h_enc^T [t][m], m = in*16+b ----------------
__global__ void combine_kernel(const float* __restrict__ Wl, const float* __restrict__ bl) {
    int idx = blockIdx.x * 256 + threadIdx.x;   // exactly SEQ*32
    int t = idx >> 5, m = idx & 31;
    int in = m >> 4, b = m & 15;
    float hf = g_hraw[(size_t)t * 64 + in * 32 + b];
    float hb = g_hraw[(size_t)(SEQ - 1 - t) * 64 + in * 32 + 16 + b];
    g_hT[idx] = fmaf(Wl[0], hf, fmaf(Wl[1], hb, bl[0]));
}

// ---------------- 4. GEMM: cp.async 2-stage pipeline, 5 CTAs/SM, split-K ----------------
// tile N=128, M=32, Kc=32. thread: 8 N rows (stride 16) x 4 M cols (2 f32x2 acc).
__global__ void __launch_bounds__(128, 5)
gemm_kernel(const float* __restrict__ A, const float* __restrict__ W, int N, int K) {
    __shared__ float sW[2][128][36];     // 36KB (rows 144B = 16B-aligned)
    __shared__ float sA[2][32][32];      // 8KB
    int t = threadIdx.x;
    int bt = blockIdx.x, bs = blockIdx.y;
    int ntiles = gridDim.x, nsp = gridDim.y;
    int n0 = bt * 128;
    int k0 = (int)(((long long)K * bs) / nsp) & ~3;
    int k1 = (bs == nsp - 1) ? K : ((int)(((long long)K * (bs + 1)) / nsp) & ~3);
    int tg = t >> 3, m0 = (t & 7) * 4;
    int nt = (k1 - k0 + 31) / 32;

    u64 acc[8][2];
#pragma unroll
    for (int j = 0; j < 8; ++j) { acc[j][0] = 0ULL; acc[j][1] = 0ULL; }

    // stage issuer: async-copy one 32-k tile into buffer `b`
    auto issue = [&](int b, int kb) {
#pragma unroll
        for (int r = 0; r < 8; ++r) {
            int n = n0 + tg + 16 * r;
            int kq = kb + m0;
            bool ok = (n < N) && (kq < k1);
            const float* src = ok ? (W + (size_t)n * K + kq) : W;
            cp16(&sW[b][tg + 16 * r][m0], src, ok);
        }
#pragma unroll
        for (int r = 0; r < 2; ++r) {
            int k = kb + tg + 16 * r;
            bool ok = (k < k1);
            const float* src = ok ? (A + (size_t)k * 32 + m0) : A;
            cp16(&sA[b][tg + 16 * r][m0], src, ok);
        }
        cp_commit();
    };

    issue(0, k0);                         // prologue
    for (int it = 0; it < nt; ++it) {
        int buf = it & 1;
        if (it + 1 < nt) {
            issue(buf ^ 1, k0 + (it + 1) * 32);
            asm volatile("cp.async.wait_group 1;");
        } else {
            asm volatile("cp.async.wait_group 0;");
        }
        __syncthreads();
#pragma unroll
        for (int k4 = 0; k4 < 8; ++k4) {
            float4 a0 = *(const float4*)&sA[buf][4 * k4 + 0][m0];
            float4 a1 = *(const float4*)&sA[buf][4 * k4 + 1][m0];
            float4 a2 = *(const float4*)&sA[buf][4 * k4 + 2][m0];
            float4 a3 = *(const float4*)&sA[buf][4 * k4 + 3][m0];
            u64 a0l = pack2(a0.x, a0.y), a0h = pack2(a0.z, a0.w);
            u64 a1l = pack2(a1.x, a1.y), a1h = pack2(a1.z, a1.w);
            u64 a2l = pack2(a2.x, a2.y), a2h = pack2(a2.z, a2.w);
            u64 a3l = pack2(a3.x, a3.y), a3h = pack2(a3.z, a3.w);
#pragma unroll
            for (int j = 0; j < 8; ++j) {
                float4 w = *(const float4*)&sW[buf][tg + 16 * j][4 * k4];
                u64 wx = dup2(w.x), wy = dup2(w.y), wz = dup2(w.z), ww = dup2(w.w);
                acc[j][0] = ffma2(wx, a0l, acc[j][0]); acc[j][1] = ffma2(wx, a0h, acc[j][1]);
                acc[j][0] = ffma2(wy, a1l, acc[j][0]); acc[j][1] = ffma2(wy, a1h, acc[j][1]);
                acc[j][0] = ffma2(wz, a2l, acc[j][0]); acc[j][1] = ffma2(wz, a2h, acc[j][1]);
                acc[j][0] = ffma2(ww, a3l, acc[j][0]); acc[j][1] = ffma2(ww, a3h, acc[j][1]);
            }
        }
        __syncthreads();
    }
    size_t base = (size_t)(bs * ntiles + bt) * 4096;
#pragma unroll
    for (int j = 0; j < 8; ++j) {
        size_t idx = base + (size_t)(tg + 16 * j) * 32 + m0;
        *(u64*)&g_part[idx]     = acc[j][0];
        *(u64*)&g_part[idx + 2] = acc[j][1];
    }
}

// ---------------- 5. split-K reduce + bias -> out [n][32] (float4) ----------------
__global__ void reduce_kernel(const float* __restrict__ bias, float* __restrict__ out,
                              int N, int ntiles, int nsplit) {
    int q = blockIdx.x * 256 + threadIdx.x;     // one float4 per thread
    if (q >= N * 8) return;
    int n = q >> 3, m4 = (q & 7) * 4;
    int bt = n >> 7, nl = n & 127;
    float b = bias[n];
    float4 s = make_float4(b, b, b, b);
    for (int sp = 0; sp < nsplit; ++sp) {
        const float4 v = *(const float4*)&g_part[((size_t)(sp * ntiles + bt) * 128 + nl) * 32 + m4];
        s.x += v.x; s.y += v.y; s.z += v.z; s.w += v.w;
    }
    *(float4*)&out[(size_t)n * 32 + m4] = s;
}

// ---------------- 6. tiny final cluster GEMM (10 x 4380) ----------------
__global__ void cluster4_kernel(const float* __restrict__ W, const float* __restrict__ bias) {
    __shared__ float red[8][32];
    int n = blockIdx.x, t = threadIdx.x;
    int m = t & 31, seg = t >> 5;
    float s = 0.0f;
    for (int k = seg; k < 4380; k += 8)
        s += g_bufA[k * 32 + m] * W[n * 4380 + k];
    red[seg][m] = s;
    __syncthreads();
    if (seg == 0) {
        float tot = bias[n];
#pragma unroll
        for (int j = 0; j < 8; ++j) tot += red[j][m];
        g_zc4[n * 32 + m] = tot;
    }
}

// ---------------- 7. instance-head L2 normalize -> d_out ----------------
__global__ void norm_kernel(float* __restrict__ out) {
    __shared__ float red[256];
    int m = blockIdx.x;                         // 0..31
    float ss = 0.0f;
    for (int f = threadIdx.x; f < 1752; f += 256) {
        float v = g_zi2[f * 32 + m]; ss += v * v;
    }
    red[threadIdx.x] = ss; __syncthreads();
    for (int s = 128; s > 0; s >>= 1) {
        if (threadIdx.x < s) red[threadIdx.x] += red[threadIdx.x + s];
        __syncthreads();
    }
    float inv = 1.0f / fmaxf(sqrtf(red[0]), 1e-12f);
    int in = m >> 4, b = m & 15;
    float* dst = out + in * (16 * 1752) + b * 1752;
    for (int f = threadIdx.x; f < 1752; f += 256)
        dst[f] = g_zi2[f * 32 + m] * inv;
}

// ---------------- 8. cluster-head softmax -> d_out ----------------
__global__ void softmax_kernel(float* __restrict__ out) {
    int m = threadIdx.x;                        // 32 threads
    float v[10]; float mx = -1e30f;
#pragma unroll
    for (int c = 0; c < 10; ++c) { v[c] = g_zc4[c * 32 + m]; mx = fmaxf(mx, v[c]); }
    float sum = 0.0f;
#pragma unroll
    for (int c = 0; c < 10; ++c) { v[c] = __expf(v[c] - mx); sum += v[c]; }
    float inv = 1.0f / sum;
    int in = m >> 4, b = m & 15;
    float* dst = out + 2 * 16 * 1752 + in * 160 + b * 10;
#pragma unroll
    for (int c = 0; c < 10; ++c) dst[c] = v[c] * inv;
}

// ---------------- launch ----------------
extern "C" void kernel_launch(void* const* d_in, const int* in_sizes, int n_in,
                              void* d_out, int out_size) {
    const float* x_t   = (const float*)d_in[0];
    const float* x_aug = (const float*)d_in[1];
    const float* Wih_f = (const float*)d_in[2];
    const float* Whh_f = (const float*)d_in[3];
    const float* b_f   = (const float*)d_in[4];
    const float* Wih_b = (const float*)d_in[5];
    const float* Whh_b = (const float*)d_in[6];
    const float* b_b   = (const float*)d_in[7];
    const float* Wl    = (const float*)d_in[8];
    const float* bl    = (const float*)d_in[9];
    const float* Wi1   = (const float*)d_in[10];
    const float* bi1   = (const float*)d_in[11];
    const float* Wi2   = (const float*)d_in[12];
    const float* bi2   = (const float*)d_in[13];
    const float* Wc1   = (const float*)d_in[14];
    const float* bc1   = (const float*)d_in[15];
    const float* Wc2   = (const float*)d_in[16];
    const float* bc2   = (const float*)d_in[17];
    const float* Wc3   = (const float*)d_in[18];
    const float* bc3   = (const float*)d_in[19];
    const float* Wc4   = (const float*)d_in[20];
    const float* bc4   = (const float*)d_in[21];
    float* out = (float*)d_out;

    float* hT   = nullptr; cudaGetSymbolAddress((void**)&hT,   g_hT);
    float* bufA = nullptr; cudaGetSymbolAddress((void**)&bufA, g_bufA);
    float* bufB = nullptr; cudaGetSymbolAddress((void**)&bufB, g_bufB);
    float* zi2  = nullptr; cudaGetSymbolAddress((void**)&zi2,  g_zi2);

    static bool attr_done = false;
    if (!attr_done) {
        cudaFuncSetAttribute(lstm_kernel, cudaFuncAttributeMaxDynamicSharedMemorySize, 122880);
        attr_done = true;
    }

    // encoder
    pre_kernel<<<(SEQ * NCH) / 256, 256>>>(x_t, x_aug, Wih_f, b_f, Wih_b, b_b);
    lstm_kernel<<<1, 256, 122880>>>(Whh_f, Whh_b);
    combine_kernel<<<(SEQ * 32) / 256, 256>>>(Wl, bl);

    // instance head: 17520 -> 8760 -> 1752
    gemm_kernel<<<dim3(69, 11), 128>>>(hT, Wi1, 8760, 17520);
    reduce_kernel<<<(8760 * 8 + 255) / 256, 256>>>(bi1, bufB, 8760, 69, 11);
    gemm_kernel<<<dim3(14, 53), 128>>>(bufB, Wi2, 1752, 8760);
    reduce_kernel<<<(1752 * 8 + 255) / 256, 256>>>(bi2, zi2, 1752, 14, 53);

    // cluster head: 17520 -> 13140 -> 8760 -> 4380 -> 10
    gemm_kernel<<<dim3(103, 7), 128>>>(hT, Wc1, 13140, 17520);
    reduce_kernel<<<(13140 * 8 + 255) / 256, 256>>>(bc1, bufA, 13140, 103, 7);
    gemm_kernel<<<dim3(69, 11), 128>>>(bufA, Wc2, 8760, 13140);
    reduce_kernel<<<(8760 * 8 + 255) / 256, 256>>>(bc2, bufB, 8760, 69, 11);
    gemm_kernel<<<dim3(35, 21), 128>>>(bufB, Wc3, 4380, 8760);
    reduce_kernel<<<(4380 * 8 + 255) / 256, 256>>>(bc3, bufA, 4380, 35, 21);
    cluster4_kernel<<<10, 256>>>(Wc4, bc4);

    // epilogues
    norm_kernel<<<32, 256>>>(out);
    softmax_kernel<<<1, 32>>>(out);
}